// round 8
// baseline (speedup 1.0000x reference)
#include <cuda_runtime.h>
#include <cuda_bf16.h>
#include <math.h>
#include <stdint.h>

#define B_SZ   4
#define T_SEQ  1024
#define DIMC   768
#define NH     12
#define DH     64
#define NROWS  (B_SZ * T_SEQ)          // 4096
#define QKV_N  (3 * DIMC)              // 2304
#define KDIM   768

#define NEG_BIG (-3.0e38f)

// ============================================================================
// Scratch (static device globals; no allocation)
// ============================================================================
__device__ float g_qkv_c [(size_t)NROWS * QKV_N];
__device__ float g_qkv_ac[(size_t)NROWS * QKV_N];
__device__ float g_attn_c [(size_t)NROWS * DIMC];
__device__ float g_attn_ac[(size_t)NROWS * DIMC];
__device__ float g_y      [(size_t)NROWS * DIMC];

// ============================================================================
// helpers
// ============================================================================
__device__ __forceinline__ uint32_t smem_u32(const void* p) {
    uint32_t a;
    asm("{ .reg .u64 t; cvta.to.shared.u64 t, %1; cvt.u32.u64 %0, t; }" : "=r"(a) : "l"(p));
    return a;
}

__device__ __forceinline__ void cp16(uint32_t dst, const void* src) {
    asm volatile("cp.async.cg.shared.global [%0], [%1], 16;" :: "r"(dst), "l"(src));
}
#define CP_COMMIT() asm volatile("cp.async.commit_group;")

__device__ __forceinline__ uint32_t f32_to_tf32(float f) {
    uint32_t r;
    asm("cvt.rna.tf32.f32 %0, %1;" : "=r"(r) : "f"(f));
    return r;
}

__device__ __forceinline__ void mma_tf32(float& d0, float& d1, float& d2, float& d3,
                                         uint32_t a0, uint32_t a1, uint32_t a2, uint32_t a3,
                                         uint32_t b0, uint32_t b1) {
    asm volatile(
        "mma.sync.aligned.m16n8k8.row.col.f32.tf32.tf32.f32 "
        "{%0,%1,%2,%3}, {%4,%5,%6,%7}, {%8,%9}, {%0,%1,%2,%3};"
        : "+f"(d0), "+f"(d1), "+f"(d2), "+f"(d3)
        : "r"(a0), "r"(a1), "r"(a2), "r"(a3), "r"(b0), "r"(b1));
}

// ============================================================================
// tf32 GEMM, cp.async 3-stage pipeline.
// MERGEK=true: K=2*KA with per-phase buffer select, adds both biases +
// residual xres, writes C0. MERGEK=false: blockIdx.z selects set.
// ============================================================================
#define BK 16
#define GSTG 3
#define ASTR 20

template<int BM_T, int BN_T, bool MERGEK>
__global__ void __launch_bounds__(256, 2) gemm_pipe(
    const float* __restrict__ A0, const float* __restrict__ A1,
    const float* __restrict__ W0, const float* __restrict__ W1,
    const float* __restrict__ bias0, const float* __restrict__ bias1,
    float* __restrict__ C0, float* __restrict__ C1,
    const float* __restrict__ xres,
    int M, int N, int K, int KA)
{
    constexpr int A_STAGE = BM_T * ASTR;
    constexpr int BSTR = BN_T + 4;
    constexpr int B_STAGE = BK * BSTR;
    constexpr int MT = BM_T / 64;
    constexpr int NT = BN_T / 16;
    constexpr int NCA = BM_T * 4;
    constexpr int NCB = BK * BN_T / 4;

    extern __shared__ float smf[];
    float* Asm = smf;
    float* Bsm = smf + GSTG * A_STAGE;
    const uint32_t sA = smem_u32(Asm);
    const uint32_t sB = smem_u32(Bsm);

    const float* Az; const float* Wz; const float* bz; float* Cz;
    if (MERGEK) { Az = A0; Wz = W0; bz = bias0; Cz = C0; }
    else {
        const int z = blockIdx.z;
        Az = z ? A1 : A0; Wz = z ? W1 : W0;
        bz = z ? bias1 : bias0; Cz = z ? C1 : C0;
    }

    const int tid  = threadIdx.x;
    const int lane = tid & 31;
    const int warp = tid >> 5;
    const int wm   = warp & 3;
    const int wn   = warp >> 2;
    const int lrow = lane >> 2;
    const int lcol = lane & 3;

    const int m0 = blockIdx.y * BM_T;
    const int n0 = blockIdx.x * BN_T;

    const int nk = K / BK;

    auto load_stage = [&](int s, int kb) {
        int k0 = kb * BK;
        const float* Au = Az; const float* Wu = Wz;
        if (MERGEK && k0 >= KA) { Au = A1; Wu = W1; k0 -= KA; }
        const uint32_t aB = sA + (uint32_t)(s * A_STAGE) * 4;
        const uint32_t bB = sB + (uint32_t)(s * B_STAGE) * 4;
#pragma unroll
        for (int i = 0; i < (NCA + 255) / 256; i++) {
            int c = tid + i * 256;
            if ((NCA % 256 == 0) || c < NCA) {
                int r = c >> 2, kc = (c & 3) * 4;
                cp16(aB + (uint32_t)(r * ASTR + kc) * 4,
                     &Au[(size_t)(m0 + r) * KA + k0 + kc]);
            }
        }
#pragma unroll
        for (int i = 0; i < (NCB + 255) / 256; i++) {
            int c = tid + i * 256;
            if ((NCB % 256 == 0) || c < NCB) {
                int kr = c / (BN_T / 4), nc = (c % (BN_T / 4)) * 4;
                cp16(bB + (uint32_t)(kr * BSTR + nc) * 4,
                     &Wu[(size_t)(k0 + kr) * N + n0 + nc]);
            }
        }
        CP_COMMIT();
    };

    float acc[MT][NT][4];
#pragma unroll
    for (int i = 0; i < MT; i++)
#pragma unroll
        for (int j = 0; j < NT; j++)
#pragma unroll
            for (int v = 0; v < 4; v++) acc[i][j][v] = 0.0f;

    load_stage(0, 0);
    load_stage(1, 1);

    for (int kb = 0; kb < nk; kb++) {
        const int s = kb % GSTG;
        if (kb + 1 < nk) asm volatile("cp.async.wait_group 1;");
        else             asm volatile("cp.async.wait_group 0;");
        __syncthreads();

        if (kb + 2 < nk) load_stage((kb + 2) % GSTG, kb + 2);

        const float* As = Asm + s * A_STAGE;
        const float* Bs = Bsm + s * B_STAGE;

#pragma unroll
        for (int ks = 0; ks < 2; ks++) {
            const int kk = ks * 8;
            uint32_t af[MT][4];
#pragma unroll
            for (int mt = 0; mt < MT; mt++) {
                int r = wm * (MT * 16) + mt * 16 + lrow;
                af[mt][0] = __float_as_uint(As[r * ASTR + kk + lcol]);
                af[mt][1] = __float_as_uint(As[(r + 8) * ASTR + kk + lcol]);
                af[mt][2] = __float_as_uint(As[r * ASTR + kk + lcol + 4]);
                af[mt][3] = __float_as_uint(As[(r + 8) * ASTR + kk + lcol + 4]);
            }
#pragma unroll
            for (int nt = 0; nt < NT; nt++) {
                int n = wn * (BN_T / 2) + nt * 8 + lrow;
                uint32_t b0 = __float_as_uint(Bs[(kk + lcol) * BSTR + n]);
                uint32_t b1 = __float_as_uint(Bs[(kk + lcol + 4) * BSTR + n]);
#pragma unroll
                for (int mt = 0; mt < MT; mt++) {
                    mma_tf32(acc[mt][nt][0], acc[mt][nt][1], acc[mt][nt][2], acc[mt][nt][3],
                             af[mt][0], af[mt][1], af[mt][2], af[mt][3], b0, b1);
                }
            }
        }
    }

    // epilogue
#pragma unroll
    for (int mt = 0; mt < MT; mt++) {
        int r = m0 + wm * (MT * 16) + mt * 16 + lrow;
#pragma unroll
        for (int nt = 0; nt < NT; nt++) {
            int c = n0 + wn * (BN_T / 2) + nt * 8 + lcol * 2;
            float2 bv = *(const float2*)&bz[c];
            float bx = bv.x, by = bv.y;
            if (MERGEK) {
                float2 b2 = *(const float2*)&bias1[c];
                bx += b2.x; by += b2.y;
            }
            float2 o0, o1;
            o0.x = acc[mt][nt][0] + bx;
            o0.y = acc[mt][nt][1] + by;
            o1.x = acc[mt][nt][2] + bx;
            o1.y = acc[mt][nt][3] + by;
            if (MERGEK) {
                float2 x0 = *(const float2*)&xres[(size_t)r * N + c];
                float2 x1 = *(const float2*)&xres[(size_t)(r + 8) * N + c];
                o0.x += x0.x; o0.y += x0.y;
                o1.x += x1.x; o1.y += x1.y;
            }
            *(float2*)&Cz[(size_t)r * N + c]       = o0;
            *(float2*)&Cz[(size_t)(r + 8) * N + c] = o1;
        }
    }
}

// ============================================================================
// Tensor-core flash attention: BN=32 key tiles, cp.async double-buffered,
// 4 CTAs/SM. Finite mask value NEG_BIG avoids NaN on fully-masked warp tiles
// (self-correcting online-softmax: junk from all-masked tiles is wiped when
// the first real key sets a normal running max, since exp(NEG_BIG - m) == 0).
// ============================================================================
#define AT_BM 64
#define AT_BN 32
#define KSTR 68
#define VSTR 72
#define PSTR 68
#define KV_STAGE (AT_BN * KSTR + AT_BN * VSTR)      // 4480 u32 per stage
#define AT_SMEM ((2 * KV_STAGE + 64 * PSTR) * 4)    // 53248 B

__global__ void __launch_bounds__(128, 4) attn_mma(
    const float* __restrict__ qkv_c, const float* __restrict__ qkv_ac,
    float* __restrict__ out_c, float* __restrict__ out_ac)
{
    extern __shared__ uint32_t asmem[];
    uint32_t* Ps = asmem + 2 * KV_STAGE;
    const uint32_t sbase = smem_u32(asmem);

    const int causal = (blockIdx.z < 4);
    const int b  = blockIdx.z & 3;
    const int h  = blockIdx.y;
    const int m0 = blockIdx.x * AT_BM;
    const float* qkv = causal ? qkv_c : qkv_ac;
    float* outp      = causal ? out_c : out_ac;

    const int tid  = threadIdx.x;
    const int warp = tid >> 5;
    const int lane = tid & 31;
    const int lrow = lane >> 2;
    const int lcol = lane & 3;

    const float* qbase = qkv + (size_t)b * T_SEQ * QKV_N + h * DH;
    const float* kbase = qbase + DIMC;
    const float* vbase = qbase + 2 * DIMC;

    const int n_start = causal ? 0 : m0;
    const int n_end   = causal ? (m0 + AT_BM) : T_SEQ;

    auto issue_kv = [&](int s, int n0) {
        const uint32_t kB = sbase + (uint32_t)(s * KV_STAGE) * 4;
        const uint32_t vB = kB + (uint32_t)(AT_BN * KSTR) * 4;
#pragma unroll
        for (int i = 0; i < 4; i++) {
            int idx = i * 128 + tid;
            int r = idx >> 4, c4 = (idx & 15) * 4;
            cp16(kB + (uint32_t)(r * KSTR + c4) * 4,
                 &kbase[(size_t)(n0 + r) * QKV_N + c4]);
            cp16(vB + (uint32_t)(r * VSTR + c4) * 4,
                 &vbase[(size_t)(n0 + r) * QKV_N + c4]);
        }
        CP_COMMIT();
    };

    issue_kv(0, n_start);

    // stage Q rows into Ps (raw f32), then read warp fragments
#pragma unroll
    for (int i = 0; i < 8; i++) {
        int idx = i * 128 + tid;
        int r = idx >> 4, c4 = (idx & 15) * 4;
        float4 q = *(const float4*)&qbase[(size_t)(m0 + r) * QKV_N + c4];
        float* p = (float*)&Ps[r * PSTR + c4];
        p[0] = q.x; p[1] = q.y; p[2] = q.z; p[3] = q.w;
    }
    __syncthreads();

    uint32_t qa[8][4];
    {
        const float* Pf = (const float*)Ps;
        const int r0 = (warp * 16 + lrow) * PSTR;
        const int r1 = r0 + 8 * PSTR;
#pragma unroll
        for (int kt = 0; kt < 8; kt++) {
            int c = kt * 8 + lcol;
            qa[kt][0] = f32_to_tf32(Pf[r0 + c]     * 0.125f);
            qa[kt][1] = f32_to_tf32(Pf[r1 + c]     * 0.125f);
            qa[kt][2] = f32_to_tf32(Pf[r0 + c + 4] * 0.125f);
            qa[kt][3] = f32_to_tf32(Pf[r1 + c + 4] * 0.125f);
        }
    }

    float o[8][4];
#pragma unroll
    for (int i = 0; i < 8; i++)
#pragma unroll
        for (int j = 0; j < 4; j++) o[i][j] = 0.0f;
    float mr0 = NEG_BIG, mr1 = NEG_BIG, l0 = 0.0f, l1 = 0.0f;

    const int r0g = m0 + warp * 16 + lrow;
    const int r1g = r0g + 8;

    int buf = 0;
    for (int n0 = n_start; n0 < n_end; n0 += AT_BN) {
        asm volatile("cp.async.wait_group 0;");
        __syncthreads();
        if (n0 + AT_BN < n_end) issue_kv(buf ^ 1, n0 + AT_BN);

        const uint32_t* Ks = asmem + buf * KV_STAGE;
        const uint32_t* Vs = Ks + AT_BN * KSTR;

        // ---- S = Q K^T  (16 rows x 32 keys per warp) ----
        float s[4][4];
#pragma unroll
        for (int nt = 0; nt < 4; nt++) {
            s[nt][0] = s[nt][1] = s[nt][2] = s[nt][3] = 0.0f;
            const int kr = (nt * 8 + lrow) * KSTR;
#pragma unroll
            for (int kt = 0; kt < 8; kt++) {
                uint32_t b0 = Ks[kr + kt * 8 + lcol];
                uint32_t b1 = Ks[kr + kt * 8 + lcol + 4];
                mma_tf32(s[nt][0], s[nt][1], s[nt][2], s[nt][3],
                         qa[kt][0], qa[kt][1], qa[kt][2], qa[kt][3], b0, b1);
            }
        }

        const bool need_mask = causal ? (n0 + AT_BN - 1 > m0 + warp * 16)
                                      : (n0 < m0 + warp * 16 + 15);
        if (need_mask) {
#pragma unroll
            for (int nt = 0; nt < 4; nt++) {
                int c0 = n0 + nt * 8 + 2 * lcol;
                int c1 = c0 + 1;
                if (causal) {
                    if (c0 > r0g) s[nt][0] = NEG_BIG;
                    if (c1 > r0g) s[nt][1] = NEG_BIG;
                    if (c0 > r1g) s[nt][2] = NEG_BIG;
                    if (c1 > r1g) s[nt][3] = NEG_BIG;
                } else {
                    if (c0 < r0g) s[nt][0] = NEG_BIG;
                    if (c1 < r0g) s[nt][1] = NEG_BIG;
                    if (c0 < r1g) s[nt][2] = NEG_BIG;
                    if (c1 < r1g) s[nt][3] = NEG_BIG;
                }
            }
        }

        // ---- online softmax (quad shuffles; all values finite) ----
        float t0 = NEG_BIG, t1 = NEG_BIG;
#pragma unroll
        for (int nt = 0; nt < 4; nt++) {
            t0 = fmaxf(t0, fmaxf(s[nt][0], s[nt][1]));
            t1 = fmaxf(t1, fmaxf(s[nt][2], s[nt][3]));
        }
        t0 = fmaxf(t0, __shfl_xor_sync(0xffffffff, t0, 1));
        t0 = fmaxf(t0, __shfl_xor_sync(0xffffffff, t0, 2));
        t1 = fmaxf(t1, __shfl_xor_sync(0xffffffff, t1, 1));
        t1 = fmaxf(t1, __shfl_xor_sync(0xffffffff, t1, 2));
        float nm0 = fmaxf(mr0, t0), nm1 = fmaxf(mr1, t1);
        float sc0 = __expf(mr0 - nm0), sc1 = __expf(mr1 - nm1);

        float sum0 = 0.0f, sum1 = 0.0f;
#pragma unroll
        for (int nt = 0; nt < 4; nt++) {
            s[nt][0] = __expf(s[nt][0] - nm0); sum0 += s[nt][0];
            s[nt][1] = __expf(s[nt][1] - nm0); sum0 += s[nt][1];
            s[nt][2] = __expf(s[nt][2] - nm1); sum1 += s[nt][2];
            s[nt][3] = __expf(s[nt][3] - nm1); sum1 += s[nt][3];
        }
        sum0 += __shfl_xor_sync(0xffffffff, sum0, 1);
        sum0 += __shfl_xor_sync(0xffffffff, sum0, 2);
        sum1 += __shfl_xor_sync(0xffffffff, sum1, 1);
        sum1 += __shfl_xor_sync(0xffffffff, sum1, 2);
        l0 = l0 * sc0 + sum0;
        l1 = l1 * sc1 + sum1;
        mr0 = nm0; mr1 = nm1;

#pragma unroll
        for (int nt = 0; nt < 8; nt++) {
            o[nt][0] *= sc0; o[nt][1] *= sc0;
            o[nt][2] *= sc1; o[nt][3] *= sc1;
        }

        // ---- P -> smem (warp-private rows, cols 0..31) ----
        {
            const int pr0 = (warp * 16 + lrow) * PSTR;
            const int pr1 = pr0 + 8 * PSTR;
#pragma unroll
            for (int nt = 0; nt < 4; nt++) {
                int c = nt * 8 + 2 * lcol;
                Ps[pr0 + c]     = f32_to_tf32(s[nt][0]);
                Ps[pr0 + c + 1] = f32_to_tf32(s[nt][1]);
                Ps[pr1 + c]     = f32_to_tf32(s[nt][2]);
                Ps[pr1 + c + 1] = f32_to_tf32(s[nt][3]);
            }
        }
        __syncwarp();

        // ---- O += P @ V  (k = 32 keys) ----
        {
            const int pr0 = (warp * 16 + lrow) * PSTR;
            const int pr1 = pr0 + 8 * PSTR;
#pragma unroll
            for (int kt = 0; kt < 4; kt++) {
                uint32_t a0 = Ps[pr0 + kt * 8 + lcol];
                uint32_t a1 = Ps[pr1 + kt * 8 + lcol];
                uint32_t a2 = Ps[pr0 + kt * 8 + lcol + 4];
                uint32_t a3 = Ps[pr1 + kt * 8 + lcol + 4];
                const int vr0 = (kt * 8 + lcol) * VSTR;
                const int vr1 = (kt * 8 + lcol + 4) * VSTR;
#pragma unroll
                for (int nt = 0; nt < 8; nt++) {
                    uint32_t b0 = Vs[vr0 + nt * 8 + lrow];
                    uint32_t b1 = Vs[vr1 + nt * 8 + lrow];
                    mma_tf32(o[nt][0], o[nt][1], o[nt][2], o[nt][3],
                             a0, a1, a2, a3, b0, b1);
                }
            }
        }
        buf ^= 1;
    }

    float inv0 = 1.0f / l0, inv1 = 1.0f / l1;
    size_t ob = (size_t)(b * T_SEQ + r0g) * DIMC + h * DH;
#pragma unroll
    for (int nt = 0; nt < 8; nt++) {
        int c = nt * 8 + 2 * lcol;
        float2 w0, w1;
        w0.x = o[nt][0] * inv0; w0.y = o[nt][1] * inv0;
        w1.x = o[nt][2] * inv1; w1.y = o[nt][3] * inv1;
        *(float2*)&outp[ob + c]            = w0;
        *(float2*)&outp[ob + 8 * DIMC + c] = w1;
    }
}

// ============================================================================
// LayerNorm on pre-summed y (residual already folded into proj epilogue)
// ============================================================================
__global__ void ln_only(const float* __restrict__ y,
                        const float* __restrict__ gamma,
                        const float* __restrict__ beta,
                        float* __restrict__ out)
{
    const int row = blockIdx.x;
    const size_t base = (size_t)row * DIMC;
    const int t = threadIdx.x;

    __shared__ float red[256];

    float v[3];
    float s = 0.0f;
#pragma unroll
    for (int i = 0; i < 3; i++) {
        v[i] = y[base + t + i * 256];
        s += v[i];
    }
    red[t] = s;
    __syncthreads();
    for (int off = 128; off > 0; off >>= 1) {
        if (t < off) red[t] += red[t + off];
        __syncthreads();
    }
    float mu = red[0] * (1.0f / DIMC);
    __syncthreads();

    float vs = 0.0f;
#pragma unroll
    for (int i = 0; i < 3; i++) {
        float d = v[i] - mu;
        vs += d * d;
    }
    red[t] = vs;
    __syncthreads();
    for (int off = 128; off > 0; off >>= 1) {
        if (t < off) red[t] += red[t + off];
        __syncthreads();
    }
    float inv = rsqrtf(red[0] * (1.0f / DIMC) + 1e-5f);

#pragma unroll
    for (int i = 0; i < 3; i++) {
        int c = t + i * 256;
        out[base + c] = (v[i] - mu) * inv * gamma[c] + beta[c];
    }
}

// ============================================================================
// launch
// ============================================================================
#define GEMM_SMEM(BM_T, BN_T) ((GSTG * ((BM_T) * ASTR + BK * ((BN_T) + 4))) * 4)

extern "C" void kernel_launch(void* const* d_in, const int* in_sizes, int n_in,
                              void* d_out, int out_size)
{
    const float* x       = (const float*)d_in[0];
    const float* Wqkv_c  = (const float*)d_in[1];
    const float* bqkv_c  = (const float*)d_in[2];
    const float* Wp_c    = (const float*)d_in[3];
    const float* bp_c    = (const float*)d_in[4];
    const float* Wqkv_ac = (const float*)d_in[5];
    const float* bqkv_ac = (const float*)d_in[6];
    const float* Wp_ac   = (const float*)d_in[7];
    const float* bp_ac   = (const float*)d_in[8];
    const float* gamma   = (const float*)d_in[9];
    const float* beta    = (const float*)d_in[10];
    float* out = (float*)d_out;

    float *qkv_c, *qkv_ac, *attn_c, *attn_ac, *ybuf;
    cudaGetSymbolAddress((void**)&qkv_c,  g_qkv_c);
    cudaGetSymbolAddress((void**)&qkv_ac, g_qkv_ac);
    cudaGetSymbolAddress((void**)&attn_c,  g_attn_c);
    cudaGetSymbolAddress((void**)&attn_ac, g_attn_ac);
    cudaGetSymbolAddress((void**)&ybuf,    g_y);

    cudaFuncSetAttribute((const void*)gemm_pipe<128,128,false>,
                         cudaFuncAttributeMaxDynamicSharedMemorySize, GEMM_SMEM(128,128));
    cudaFuncSetAttribute((const void*)gemm_pipe<64,64,true>,
                         cudaFuncAttributeMaxDynamicSharedMemorySize, GEMM_SMEM(64,64));
    cudaFuncSetAttribute((const void*)attn_mma,
                         cudaFuncAttributeMaxDynamicSharedMemorySize, AT_SMEM);

    dim3 blk256(256);

    // ---- QKV GEMMs, both branches in one launch (128x128 tiles) ----
    gemm_pipe<128,128,false><<<dim3(QKV_N / 128, NROWS / 128, 2), blk256,
                               GEMM_SMEM(128,128)>>>(
        x, x, Wqkv_c, Wqkv_ac, bqkv_c, bqkv_ac, qkv_c, qkv_ac, nullptr,
        NROWS, QKV_N, KDIM, KDIM);

    // ---- attention: both branches in one launch ----
    attn_mma<<<dim3(T_SEQ / AT_BM, NH, 2 * B_SZ), dim3(128), AT_SMEM>>>(
        qkv_c, qkv_ac, attn_c, attn_ac);

    // ---- merged proj GEMM: y = x + [attn_c|attn_ac] @ [Wp_c;Wp_ac] + biases ----
    gemm_pipe<64,64,true><<<dim3(DIMC / 64, NROWS / 64, 1), blk256,
                            GEMM_SMEM(64,64)>>>(
        attn_c, attn_ac, Wp_c, Wp_ac, bp_c, bp_ac, ybuf, ybuf, x,
        NROWS, DIMC, 2 * KDIM, KDIM);

    // ---- layernorm ----
    ln_only<<<NROWS, blk256>>>(ybuf, gamma, beta, out);
}

// round 9
// speedup vs baseline: 1.1595x; 1.1595x over previous
#include <cuda_runtime.h>
#include <cuda_bf16.h>
#include <math.h>
#include <stdint.h>

#define B_SZ   4
#define T_SEQ  1024
#define DIMC   768
#define NH     12
#define DH     64
#define NROWS  (B_SZ * T_SEQ)          // 4096
#define QKV_N  (3 * DIMC)              // 2304
#define KDIM   768

#define NEG_BIG (-3.0e38f)

// ============================================================================
// Scratch (static device globals; no allocation)
// ============================================================================
__device__ float g_qkv_c [(size_t)NROWS * QKV_N];
__device__ float g_qkv_ac[(size_t)NROWS * QKV_N];
__device__ float g_attn_c [(size_t)NROWS * DIMC];
__device__ float g_attn_ac[(size_t)NROWS * DIMC];
__device__ float g_proj_c [(size_t)NROWS * DIMC];
__device__ float g_proj_ac[(size_t)NROWS * DIMC];
__device__ float g_wtq_c [(size_t)QKV_N * KDIM];   // Wqkv_c^T  [2304][768]
__device__ float g_wtq_ac[(size_t)QKV_N * KDIM];
__device__ float g_wtp_c [(size_t)DIMC * KDIM];    // Wp_c^T    [768][768]
__device__ float g_wtp_ac[(size_t)DIMC * KDIM];

// ============================================================================
// helpers
// ============================================================================
__device__ __forceinline__ uint32_t smem_u32(const void* p) {
    uint32_t a;
    asm("{ .reg .u64 t; cvta.to.shared.u64 t, %1; cvt.u32.u64 %0, t; }" : "=r"(a) : "l"(p));
    return a;
}

__device__ __forceinline__ void cp16(uint32_t dst, const void* src) {
    asm volatile("cp.async.cg.shared.global [%0], [%1], 16;" :: "r"(dst), "l"(src));
}
#define CP_COMMIT() asm volatile("cp.async.commit_group;")

__device__ __forceinline__ uint32_t f32_to_tf32(float f) {
    uint32_t r;
    asm("cvt.rna.tf32.f32 %0, %1;" : "=r"(r) : "f"(f));
    return r;
}

__device__ __forceinline__ void mma_tf32(float& d0, float& d1, float& d2, float& d3,
                                         uint32_t a0, uint32_t a1, uint32_t a2, uint32_t a3,
                                         uint32_t b0, uint32_t b1) {
    asm volatile(
        "mma.sync.aligned.m16n8k8.row.col.f32.tf32.tf32.f32 "
        "{%0,%1,%2,%3}, {%4,%5,%6,%7}, {%8,%9}, {%0,%1,%2,%3};"
        : "+f"(d0), "+f"(d1), "+f"(d2), "+f"(d3)
        : "r"(a0), "r"(a1), "r"(a2), "r"(a3), "r"(b0), "r"(b1));
}

__device__ __forceinline__ void ldsm_x4(uint32_t& r0, uint32_t& r1, uint32_t& r2, uint32_t& r3,
                                        uint32_t addr) {
    asm volatile("ldmatrix.sync.aligned.m8n8.x4.shared.b16 {%0,%1,%2,%3}, [%4];"
                 : "=r"(r0), "=r"(r1), "=r"(r2), "=r"(r3) : "r"(addr));
}

// ============================================================================
// Weight transpose: W[K][N] f32 -> Wt[N][K] f32 (32x32 tiles, block (32,8))
// ============================================================================
__global__ void transpose_f32(const float* __restrict__ W,
                              float* __restrict__ Wt, int K, int N)
{
    __shared__ float t[32][33];
    int nb = blockIdx.x * 32, kb = blockIdx.y * 32;
    int tx = threadIdx.x, ty = threadIdx.y;
#pragma unroll
    for (int i = 0; i < 4; i++)
        t[ty + i * 8][tx] = W[(size_t)(kb + ty + i * 8) * N + nb + tx];
    __syncthreads();
#pragma unroll
    for (int i = 0; i < 4; i++)
        Wt[(size_t)(nb + ty + i * 8) * K + kb + tx] = t[tx][ty + i * 8];
}

// ============================================================================
// tf32 GEMM with ldmatrix fragments. C[M,N] = A[M,K] @ Wt[N,K]^T + bias.
// Both A and B stages are rows x (BK+4) k-contiguous; fragments via LDSM.
// cp.async 3-stage pipeline; z selects the (A,Wt,bias,C) set.
// 8 warps: wm = warp&3 (m), wn = warp>>2 (n); warp tile 32 x (BN_T/2).
// ============================================================================
#define BK 16
#define GSTG 3
#define RSTR 20

template<int BM_T, int BN_T>
__global__ void __launch_bounds__(256, 2) gemm_ldsm(
    const float* __restrict__ A0, const float* __restrict__ A1,
    const float* __restrict__ Wt0, const float* __restrict__ Wt1,
    const float* __restrict__ bias0, const float* __restrict__ bias1,
    float* __restrict__ C0, float* __restrict__ C1,
    int M, int N, int K)
{
    constexpr int A_STAGE = BM_T * RSTR;
    constexpr int B_STAGE = BN_T * RSTR;
    constexpr int STAGE   = A_STAGE + B_STAGE;
    constexpr int NT  = BN_T / 16;           // n-subtiles per warp
    constexpr int NCH = (BM_T + BN_T) * 4;   // 16B chunks per stage

    extern __shared__ float smf[];
    const uint32_t sbase = smem_u32(smf);

    const int z = blockIdx.z;
    const float* A    = z ? A1 : A0;
    const float* Wt   = z ? Wt1 : Wt0;
    const float* bias = z ? bias1 : bias0;
    float*       C    = z ? C1 : C0;

    const int tid  = threadIdx.x;
    const int lane = tid & 31;
    const int warp = tid >> 5;
    const int wm   = warp & 3;
    const int wn   = warp >> 2;
    const int lrow = lane >> 2;
    const int lcol = lane & 3;

    const int m0 = blockIdx.y * BM_T;
    const int n0 = blockIdx.x * BN_T;

    const int nk = K / BK;

    auto load_stage = [&](int s, int kb) {
        const int k0 = kb * BK;
        const uint32_t stB = sbase + (uint32_t)(s * STAGE) * 4;
#pragma unroll
        for (int i = 0; i < NCH / 256; i++) {
            int c = tid + i * 256;
            if (c < BM_T * 4) {
                int r = c >> 2, kc = (c & 3) * 4;
                cp16(stB + (uint32_t)(r * RSTR + kc) * 4,
                     &A[(size_t)(m0 + r) * K + k0 + kc]);
            } else {
                int c2 = c - BM_T * 4;
                int r = c2 >> 2, kc = (c2 & 3) * 4;
                cp16(stB + (uint32_t)(A_STAGE + r * RSTR + kc) * 4,
                     &Wt[(size_t)(n0 + r) * K + k0 + kc]);
            }
        }
        CP_COMMIT();
    };

    float acc[2][NT][4];
#pragma unroll
    for (int i = 0; i < 2; i++)
#pragma unroll
        for (int j = 0; j < NT; j++)
#pragma unroll
            for (int v = 0; v < 4; v++) acc[i][j][v] = 0.0f;

    // LDSM lane addressing (bank-clean for stride-20 rows):
    // A tiles: row = base + (lane & 15), col = kk + ((lane >> 4) << 2)
    const int a_lrow = (lane & 15);
    const int a_lcol = (lane >> 4) << 2;
    // B tiles: row = nb + (lane & 7) + ((lane >> 4) << 3), col = kk + (((lane >> 3) & 1) << 2)
    const int b_lrow = (lane & 7) + ((lane >> 4) << 3);
    const int b_lcol = ((lane >> 3) & 1) << 2;

    load_stage(0, 0);
    load_stage(1, 1);

    for (int kb = 0; kb < nk; kb++) {
        const int s = kb % GSTG;
        if (kb + 1 < nk) asm volatile("cp.async.wait_group 1;");
        else             asm volatile("cp.async.wait_group 0;");
        __syncthreads();

        if (kb + 2 < nk) load_stage((kb + 2) % GSTG, kb + 2);

        const uint32_t aB = sbase + (uint32_t)(s * STAGE) * 4;
        const uint32_t bB = aB + (uint32_t)A_STAGE * 4;

#pragma unroll
        for (int ks = 0; ks < 2; ks++) {
            const int kk = ks * 8;
            // A fragments: 2 m-subtiles
            uint32_t af[2][4];
#pragma unroll
            for (int mt = 0; mt < 2; mt++) {
                uint32_t addr = aB +
                    (uint32_t)((wm * 32 + mt * 16 + a_lrow) * RSTR + kk + a_lcol) * 4;
                ldsm_x4(af[mt][0], af[mt][1], af[mt][2], af[mt][3], addr);
            }
            // B fragments: NT/2 ldmatrix.x4, each covers 2 n-subtiles
#pragma unroll
            for (int j = 0; j < NT / 2; j++) {
                uint32_t b0, b1, b2, b3;
                uint32_t addr = bB +
                    (uint32_t)((wn * (BN_T / 2) + j * 16 + b_lrow) * RSTR + kk + b_lcol) * 4;
                ldsm_x4(b0, b1, b2, b3, addr);
#pragma unroll
                for (int mt = 0; mt < 2; mt++) {
                    mma_tf32(acc[mt][2*j][0], acc[mt][2*j][1], acc[mt][2*j][2], acc[mt][2*j][3],
                             af[mt][0], af[mt][1], af[mt][2], af[mt][3], b0, b1);
                    mma_tf32(acc[mt][2*j+1][0], acc[mt][2*j+1][1], acc[mt][2*j+1][2], acc[mt][2*j+1][3],
                             af[mt][0], af[mt][1], af[mt][2], af[mt][3], b2, b3);
                }
            }
        }
    }

    // epilogue
#pragma unroll
    for (int mt = 0; mt < 2; mt++) {
        int r = m0 + wm * 32 + mt * 16 + lrow;
#pragma unroll
        for (int nt = 0; nt < NT; nt++) {
            int c = n0 + wn * (BN_T / 2) + nt * 8 + lcol * 2;
            float2 bv = *(const float2*)&bias[c];
            float2 o0, o1;
            o0.x = acc[mt][nt][0] + bv.x;
            o0.y = acc[mt][nt][1] + bv.y;
            o1.x = acc[mt][nt][2] + bv.x;
            o1.y = acc[mt][nt][3] + bv.y;
            *(float2*)&C[(size_t)r * N + c]       = o0;
            *(float2*)&C[(size_t)(r + 8) * N + c] = o1;
        }
    }
}

// ============================================================================
// Tensor-core flash attention (round-5 proven config: BN=64, sync loads,
// 53KB smem -> 4 CTA/SM) + NEG_BIG mask hardening + heavy-block-first remap.
// ============================================================================
#define AT_BM 64
#define AT_BN 64
#define KSTR 68
#define VSTR 72
#define PSTR 68
#define AT_SMEM ((64 * KSTR + 64 * VSTR + 64 * PSTR) * 4)   // 53248 B

__global__ void __launch_bounds__(128) attn_mma(
    const float* __restrict__ qkv_c, const float* __restrict__ qkv_ac,
    float* __restrict__ out_c, float* __restrict__ out_ac)
{
    extern __shared__ uint32_t asmem[];
    uint32_t* Ks = asmem;
    uint32_t* Vs = Ks + 64 * KSTR;
    uint32_t* Ps = Vs + 64 * VSTR;

    const int causal = (blockIdx.z < 4);
    const int b  = blockIdx.z & 3;
    const int h  = blockIdx.y;
    // heavy blocks first: causal work grows with m0, so reverse its order
    const int m0 = (causal ? (gridDim.x - 1 - blockIdx.x) : blockIdx.x) * AT_BM;
    const float* qkv = causal ? qkv_c : qkv_ac;
    float* outp      = causal ? out_c : out_ac;

    const int tid  = threadIdx.x;
    const int warp = tid >> 5;
    const int lane = tid & 31;
    const int lrow = lane >> 2;
    const int lcol = lane & 3;

    const float* qbase = qkv + (size_t)b * T_SEQ * QKV_N + h * DH;
    const float* kbase = qbase + DIMC;
    const float* vbase = qbase + 2 * DIMC;

    // stage Q rows into Ps (raw f32), then read warp fragments
#pragma unroll
    for (int i = 0; i < 8; i++) {
        int idx = i * 128 + tid;
        int r = idx >> 4, c4 = (idx & 15) * 4;
        float4 q = *(const float4*)&qbase[(size_t)(m0 + r) * QKV_N + c4];
        float* p = (float*)&Ps[r * PSTR + c4];
        p[0] = q.x; p[1] = q.y; p[2] = q.z; p[3] = q.w;
    }
    __syncthreads();

    uint32_t qa[8][4];
    {
        const float* Pf = (const float*)Ps;
        const int r0 = (warp * 16 + lrow) * PSTR;
        const int r1 = r0 + 8 * PSTR;
#pragma unroll
        for (int kt = 0; kt < 8; kt++) {
            int c = kt * 8 + lcol;
            qa[kt][0] = f32_to_tf32(Pf[r0 + c]     * 0.125f);
            qa[kt][1] = f32_to_tf32(Pf[r1 + c]     * 0.125f);
            qa[kt][2] = f32_to_tf32(Pf[r0 + c + 4] * 0.125f);
            qa[kt][3] = f32_to_tf32(Pf[r1 + c + 4] * 0.125f);
        }
    }
    __syncthreads();

    float o[8][4];
#pragma unroll
    for (int i = 0; i < 8; i++)
#pragma unroll
        for (int j = 0; j < 4; j++) o[i][j] = 0.0f;
    float mr0 = NEG_BIG, mr1 = NEG_BIG, l0 = 0.0f, l1 = 0.0f;

    const int r0g = m0 + warp * 16 + lrow;
    const int r1g = r0g + 8;

    const int n_start = causal ? 0 : m0;
    const int n_end   = causal ? (m0 + AT_BM) : T_SEQ;

    for (int n0 = n_start; n0 < n_end; n0 += AT_BN) {
        // ---- load K, V tiles to smem (pre-converted tf32) ----
#pragma unroll
        for (int i = 0; i < 8; i++) {
            int idx = i * 128 + tid;
            int r = idx >> 4, c4 = (idx & 15) * 4;
            float4 kv = *(const float4*)&kbase[(size_t)(n0 + r) * QKV_N + c4];
            uint32_t* kp = &Ks[r * KSTR + c4];
            kp[0] = f32_to_tf32(kv.x); kp[1] = f32_to_tf32(kv.y);
            kp[2] = f32_to_tf32(kv.z); kp[3] = f32_to_tf32(kv.w);
            float4 vv = *(const float4*)&vbase[(size_t)(n0 + r) * QKV_N + c4];
            uint32_t* vp = &Vs[r * VSTR + c4];
            vp[0] = f32_to_tf32(vv.x); vp[1] = f32_to_tf32(vv.y);
            vp[2] = f32_to_tf32(vv.z); vp[3] = f32_to_tf32(vv.w);
        }
        __syncthreads();

        // ---- S = Q K^T ----
        float s[8][4];
#pragma unroll
        for (int nt = 0; nt < 8; nt++) {
            s[nt][0] = s[nt][1] = s[nt][2] = s[nt][3] = 0.0f;
            const int kr = (nt * 8 + lrow) * KSTR;
#pragma unroll
            for (int kt = 0; kt < 8; kt++) {
                uint32_t b0 = Ks[kr + kt * 8 + lcol];
                uint32_t b1 = Ks[kr + kt * 8 + lcol + 4];
                mma_tf32(s[nt][0], s[nt][1], s[nt][2], s[nt][3],
                         qa[kt][0], qa[kt][1], qa[kt][2], qa[kt][3], b0, b1);
            }
        }

        const bool need_mask = causal ? (n0 + AT_BN - 1 > m0 + warp * 16)
                                      : (n0 < m0 + warp * 16 + 15);
        if (need_mask) {
#pragma unroll
            for (int nt = 0; nt < 8; nt++) {
                int c0 = n0 + nt * 8 + 2 * lcol;
                int c1 = c0 + 1;
                if (causal) {
                    if (c0 > r0g) s[nt][0] = NEG_BIG;
                    if (c1 > r0g) s[nt][1] = NEG_BIG;
                    if (c0 > r1g) s[nt][2] = NEG_BIG;
                    if (c1 > r1g) s[nt][3] = NEG_BIG;
                } else {
                    if (c0 < r0g) s[nt][0] = NEG_BIG;
                    if (c1 < r0g) s[nt][1] = NEG_BIG;
                    if (c0 < r1g) s[nt][2] = NEG_BIG;
                    if (c1 < r1g) s[nt][3] = NEG_BIG;
                }
            }
        }

        // ---- online softmax (quad shuffles; all values finite) ----
        float t0 = NEG_BIG, t1 = NEG_BIG;
#pragma unroll
        for (int nt = 0; nt < 8; nt++) {
            t0 = fmaxf(t0, fmaxf(s[nt][0], s[nt][1]));
            t1 = fmaxf(t1, fmaxf(s[nt][2], s[nt][3]));
        }
        t0 = fmaxf(t0, __shfl_xor_sync(0xffffffff, t0, 1));
        t0 = fmaxf(t0, __shfl_xor_sync(0xffffffff, t0, 2));
        t1 = fmaxf(t1, __shfl_xor_sync(0xffffffff, t1, 1));
        t1 = fmaxf(t1, __shfl_xor_sync(0xffffffff, t1, 2));
        float nm0 = fmaxf(mr0, t0), nm1 = fmaxf(mr1, t1);
        float sc0 = __expf(mr0 - nm0), sc1 = __expf(mr1 - nm1);

        float sum0 = 0.0f, sum1 = 0.0f;
#pragma unroll
        for (int nt = 0; nt < 8; nt++) {
            s[nt][0] = __expf(s[nt][0] - nm0); sum0 += s[nt][0];
            s[nt][1] = __expf(s[nt][1] - nm0); sum0 += s[nt][1];
            s[nt][2] = __expf(s[nt][2] - nm1); sum1 += s[nt][2];
            s[nt][3] = __expf(s[nt][3] - nm1); sum1 += s[nt][3];
        }
        sum0 += __shfl_xor_sync(0xffffffff, sum0, 1);
        sum0 += __shfl_xor_sync(0xffffffff, sum0, 2);
        sum1 += __shfl_xor_sync(0xffffffff, sum1, 1);
        sum1 += __shfl_xor_sync(0xffffffff, sum1, 2);
        l0 = l0 * sc0 + sum0;
        l1 = l1 * sc1 + sum1;
        mr0 = nm0; mr1 = nm1;

#pragma unroll
        for (int nt = 0; nt < 8; nt++) {
            o[nt][0] *= sc0; o[nt][1] *= sc0;
            o[nt][2] *= sc1; o[nt][3] *= sc1;
        }

        // ---- P -> smem (warp-private region, tf32) ----
        {
            const int pr0 = (warp * 16 + lrow) * PSTR;
            const int pr1 = pr0 + 8 * PSTR;
#pragma unroll
            for (int nt = 0; nt < 8; nt++) {
                int c = nt * 8 + 2 * lcol;
                Ps[pr0 + c]     = f32_to_tf32(s[nt][0]);
                Ps[pr0 + c + 1] = f32_to_tf32(s[nt][1]);
                Ps[pr1 + c]     = f32_to_tf32(s[nt][2]);
                Ps[pr1 + c + 1] = f32_to_tf32(s[nt][3]);
            }
        }
        __syncwarp();

        // ---- O += P @ V ----
        {
            const int pr0 = (warp * 16 + lrow) * PSTR;
            const int pr1 = pr0 + 8 * PSTR;
#pragma unroll
            for (int kt = 0; kt < 8; kt++) {
                uint32_t a0 = Ps[pr0 + kt * 8 + lcol];
                uint32_t a1 = Ps[pr1 + kt * 8 + lcol];
                uint32_t a2 = Ps[pr0 + kt * 8 + lcol + 4];
                uint32_t a3 = Ps[pr1 + kt * 8 + lcol + 4];
                const int vr0 = (kt * 8 + lcol) * VSTR;
                const int vr1 = (kt * 8 + lcol + 4) * VSTR;
#pragma unroll
                for (int nt = 0; nt < 8; nt++) {
                    uint32_t b0 = Vs[vr0 + nt * 8 + lrow];
                    uint32_t b1 = Vs[vr1 + nt * 8 + lrow];
                    mma_tf32(o[nt][0], o[nt][1], o[nt][2], o[nt][3],
                             a0, a1, a2, a3, b0, b1);
                }
            }
        }
        __syncthreads();
    }

    float inv0 = 1.0f / l0, inv1 = 1.0f / l1;
    size_t ob = (size_t)(b * T_SEQ + r0g) * DIMC + h * DH;
#pragma unroll
    for (int nt = 0; nt < 8; nt++) {
        int c = nt * 8 + 2 * lcol;
        float2 w0, w1;
        w0.x = o[nt][0] * inv0; w0.y = o[nt][1] * inv0;
        w1.x = o[nt][2] * inv1; w1.y = o[nt][3] * inv1;
        *(float2*)&outp[ob + c]            = w0;
        *(float2*)&outp[ob + 8 * DIMC + c] = w1;
    }
}

// ============================================================================
// Fused residual + LayerNorm (round-5 proven)
// ============================================================================
__global__ void residual_ln(const float* __restrict__ x,
                            const float* __restrict__ pc,
                            const float* __restrict__ pac,
                            const float* __restrict__ gamma,
                            const float* __restrict__ beta,
                            float* __restrict__ out)
{
    const int row = blockIdx.x;
    const size_t base = (size_t)row * DIMC;
    const int t = threadIdx.x;

    __shared__ float red[256];

    float y[3];
    float s = 0.0f;
#pragma unroll
    for (int i = 0; i < 3; i++) {
        int c = t + i * 256;
        y[i] = x[base + c] + pc[base + c] + pac[base + c];
        s += y[i];
    }
    red[t] = s;
    __syncthreads();
    for (int off = 128; off > 0; off >>= 1) {
        if (t < off) red[t] += red[t + off];
        __syncthreads();
    }
    float mu = red[0] * (1.0f / DIMC);
    __syncthreads();

    float vs = 0.0f;
#pragma unroll
    for (int i = 0; i < 3; i++) {
        float d = y[i] - mu;
        vs += d * d;
    }
    red[t] = vs;
    __syncthreads();
    for (int off = 128; off > 0; off >>= 1) {
        if (t < off) red[t] += red[t + off];
        __syncthreads();
    }
    float inv = rsqrtf(red[0] * (1.0f / DIMC) + 1e-5f);

#pragma unroll
    for (int i = 0; i < 3; i++) {
        int c = t + i * 256;
        out[base + c] = (y[i] - mu) * inv * gamma[c] + beta[c];
    }
}

// ============================================================================
// launch
// ============================================================================
#define GEMM_SMEM(BM_T, BN_T) ((GSTG * ((BM_T) + (BN_T)) * RSTR) * 4)

extern "C" void kernel_launch(void* const* d_in, const int* in_sizes, int n_in,
                              void* d_out, int out_size)
{
    const float* x       = (const float*)d_in[0];
    const float* Wqkv_c  = (const float*)d_in[1];
    const float* bqkv_c  = (const float*)d_in[2];
    const float* Wp_c    = (const float*)d_in[3];
    const float* bp_c    = (const float*)d_in[4];
    const float* Wqkv_ac = (const float*)d_in[5];
    const float* bqkv_ac = (const float*)d_in[6];
    const float* Wp_ac   = (const float*)d_in[7];
    const float* bp_ac   = (const float*)d_in[8];
    const float* gamma   = (const float*)d_in[9];
    const float* beta    = (const float*)d_in[10];
    float* out = (float*)d_out;

    float *qkv_c, *qkv_ac, *attn_c, *attn_ac, *proj_c, *proj_ac;
    float *wtq_c, *wtq_ac, *wtp_c, *wtp_ac;
    cudaGetSymbolAddress((void**)&qkv_c,  g_qkv_c);
    cudaGetSymbolAddress((void**)&qkv_ac, g_qkv_ac);
    cudaGetSymbolAddress((void**)&attn_c,  g_attn_c);
    cudaGetSymbolAddress((void**)&attn_ac, g_attn_ac);
    cudaGetSymbolAddress((void**)&proj_c,  g_proj_c);
    cudaGetSymbolAddress((void**)&proj_ac, g_proj_ac);
    cudaGetSymbolAddress((void**)&wtq_c,  g_wtq_c);
    cudaGetSymbolAddress((void**)&wtq_ac, g_wtq_ac);
    cudaGetSymbolAddress((void**)&wtp_c,  g_wtp_c);
    cudaGetSymbolAddress((void**)&wtp_ac, g_wtp_ac);

    cudaFuncSetAttribute((const void*)gemm_ldsm<128,128>,
                         cudaFuncAttributeMaxDynamicSharedMemorySize, GEMM_SMEM(128,128));
    cudaFuncSetAttribute((const void*)gemm_ldsm<128,64>,
                         cudaFuncAttributeMaxDynamicSharedMemorySize, GEMM_SMEM(128,64));
    cudaFuncSetAttribute((const void*)attn_mma,
                         cudaFuncAttributeMaxDynamicSharedMemorySize, AT_SMEM);

    dim3 blk256(256);
    dim3 tb(32, 8);

    // ---- weight transposes ----
    transpose_f32<<<dim3(QKV_N / 32, KDIM / 32), tb>>>(Wqkv_c,  wtq_c,  KDIM, QKV_N);
    transpose_f32<<<dim3(QKV_N / 32, KDIM / 32), tb>>>(Wqkv_ac, wtq_ac, KDIM, QKV_N);
    transpose_f32<<<dim3(DIMC / 32, KDIM / 32), tb>>>(Wp_c,  wtp_c,  KDIM, DIMC);
    transpose_f32<<<dim3(DIMC / 32, KDIM / 32), tb>>>(Wp_ac, wtp_ac, KDIM, DIMC);

    // ---- QKV GEMMs, both branches (128x128, ldmatrix fragments) ----
    gemm_ldsm<128,128><<<dim3(QKV_N / 128, NROWS / 128, 2), blk256,
                         GEMM_SMEM(128,128)>>>(
        x, x, wtq_c, wtq_ac, bqkv_c, bqkv_ac, qkv_c, qkv_ac,
        NROWS, QKV_N, KDIM);

    // ---- attention: both branches in one launch ----
    attn_mma<<<dim3(T_SEQ / AT_BM, NH, 2 * B_SZ), dim3(128), AT_SMEM>>>(
        qkv_c, qkv_ac, attn_c, attn_ac);

    // ---- proj GEMMs, both branches (128x64) ----
    gemm_ldsm<128,64><<<dim3(DIMC / 64, NROWS / 128, 2), blk256,
                        GEMM_SMEM(128,64)>>>(
        attn_c, attn_ac, wtp_c, wtp_ac, bp_c, bp_ac, proj_c, proj_ac,
        NROWS, DIMC, KDIM);

    // ---- fused residual + layernorm ----
    residual_ln<<<NROWS, blk256>>>(x, proj_c, proj_ac, gamma, beta, out);
}